// round 1
// baseline (speedup 1.0000x reference)
#include <cuda_runtime.h>
#include <cstdint>

#define N_NODES 50000
#define N_EDGES 800000
#define D 96
#define C4 (D / 4)  // 24 float4 chunks per row

// Scratch (no allocations allowed): neighbor-transformed features + degree norm.
__device__ float g_h[(size_t)N_NODES * D];
__device__ float g_dinv[N_NODES];
__device__ int   g_deg[N_NODES];

// ---------------------------------------------------------------------------
// 1) zero degree counters
__global__ void k_zero_deg() {
    int i = blockIdx.x * blockDim.x + threadIdx.x;
    if (i < N_NODES) g_deg[i] = 0;
}

// 2) in-degree count (dst-based, matches reference segment_sum over dst)
__global__ void k_count_deg(const int* __restrict__ dst) {
    int e = blockIdx.x * blockDim.x + threadIdx.x;
    if (e < N_EDGES) atomicAdd(&g_deg[dst[e]], 1);
}

// 3) dinv = rsqrt(max(deg, 1))
__global__ void k_dinv() {
    int i = blockIdx.x * blockDim.x + threadIdx.x;
    if (i < N_NODES) {
        float d = (float)g_deg[i];
        g_dinv[i] = rsqrtf(fmaxf(d, 1.0f));
    }
}

// ---------------------------------------------------------------------------
// 4) GEMM: out[i][j] = sum_k x[i][k] * W[j][k] + b[j]
// One node per thread; x row held in registers; W in shared (broadcast LDS).
// TO_GH=true writes to the g_h scratch, else to the supplied out pointer.
template <bool TO_GH>
__global__ void __launch_bounds__(128)
k_gemm(const float* __restrict__ x, const float* __restrict__ W,
       const float* __restrict__ b, float* __restrict__ out_param) {
    __shared__ float sW[D * D];
    __shared__ float sb[D];
    for (int t = threadIdx.x; t < D * D; t += blockDim.x) sW[t] = W[t];
    if (threadIdx.x < D) sb[threadIdx.x] = b[threadIdx.x];
    __syncthreads();

    int i = blockIdx.x * blockDim.x + threadIdx.x;
    if (i >= N_NODES) return;

    float xr[D];
    const float4* xrow = reinterpret_cast<const float4*>(x + (size_t)i * D);
#pragma unroll
    for (int k = 0; k < C4; k++) {
        float4 t = xrow[k];
        xr[4 * k + 0] = t.x; xr[4 * k + 1] = t.y;
        xr[4 * k + 2] = t.z; xr[4 * k + 3] = t.w;
    }

    float* optr = TO_GH ? g_h : out_param;
    float4* orow = reinterpret_cast<float4*>(optr + (size_t)i * D);

#pragma unroll 1
    for (int j = 0; j < D; j += 4) {
        float a0 = sb[j + 0], a1 = sb[j + 1], a2 = sb[j + 2], a3 = sb[j + 3];
        const float* w0 = &sW[(j + 0) * D];
        const float* w1 = &sW[(j + 1) * D];
        const float* w2 = &sW[(j + 2) * D];
        const float* w3 = &sW[(j + 3) * D];
#pragma unroll
        for (int k = 0; k < D; k++) {
            float xv = xr[k];
            a0 = fmaf(xv, w0[k], a0);
            a1 = fmaf(xv, w1[k], a1);
            a2 = fmaf(xv, w2[k], a2);
            a3 = fmaf(xv, w3[k], a3);
        }
        float4 r; r.x = a0; r.y = a1; r.z = a2; r.w = a3;
        orow[j / 4] = r;
    }
}

// ---------------------------------------------------------------------------
// 5) edge scatter: out[dst] += norm * h[src], 128-bit vector reductions.
// Work item = (edge, chunk): 24 float4 chunks per edge, consecutive threads
// cover one edge's row -> coalesced h gather.
__global__ void k_scatter(const int* __restrict__ src, const int* __restrict__ dst,
                          float* __restrict__ out) {
    int idx = blockIdx.x * blockDim.x + threadIdx.x;  // < 19.2M, fits int32
    const int total = N_EDGES * C4;
    if (idx >= total) return;
    int e = idx / C4;
    int c = idx - e * C4;
    int s = src[e];
    int d = dst[e];
    float norm = g_dinv[s] * g_dinv[d];
    const float4* hv = reinterpret_cast<const float4*>(g_h);
    float4 v = hv[(size_t)s * C4 + c];
    v.x *= norm; v.y *= norm; v.z *= norm; v.w *= norm;
    float* p = out + (size_t)d * D + c * 4;
    asm volatile("red.global.add.v4.f32 [%0], {%1,%2,%3,%4};"
                 :: "l"(p), "f"(v.x), "f"(v.y), "f"(v.z), "f"(v.w)
                 : "memory");
}

// 6) in-place ReLU
__global__ void k_relu(float* __restrict__ out) {
    int idx = blockIdx.x * blockDim.x + threadIdx.x;
    const int total = N_NODES * C4;
    if (idx >= total) return;
    float4* p = reinterpret_cast<float4*>(out) + idx;
    float4 v = *p;
    v.x = fmaxf(v.x, 0.0f);
    v.y = fmaxf(v.y, 0.0f);
    v.z = fmaxf(v.z, 0.0f);
    v.w = fmaxf(v.w, 0.0f);
    *p = v;
}

// ---------------------------------------------------------------------------
extern "C" void kernel_launch(void* const* d_in, const int* in_sizes, int n_in,
                              void* d_out, int out_size) {
    const float* x     = (const float*)d_in[0];
    const int*   edges = (const int*)d_in[1];
    const float* Wlin  = (const float*)d_in[2];
    const float* blin  = (const float*)d_in[3];
    const float* Wroot = (const float*)d_in[4];
    const float* broot = (const float*)d_in[5];
    float* out = (float*)d_out;

    const int* src = edges;            // edge_index[0, :]
    const int* dst = edges + N_EDGES;  // edge_index[1, :]

    k_zero_deg<<<(N_NODES + 255) / 256, 256>>>();
    k_count_deg<<<(N_EDGES + 255) / 256, 256>>>(dst);
    k_dinv<<<(N_NODES + 255) / 256, 256>>>();

    // root GEMM writes straight into d_out (also serves as scatter init)
    k_gemm<false><<<(N_NODES + 127) / 128, 128>>>(x, Wroot, broot, out);
    // neighbor GEMM into scratch
    k_gemm<true><<<(N_NODES + 127) / 128, 128>>>(x, Wlin, blin, nullptr);

    k_scatter<<<(N_EDGES * C4 + 255) / 256, 256>>>(src, dst, out);
    k_relu<<<(N_NODES * C4 + 255) / 256, 256>>>(out);
}

// round 2
// speedup vs baseline: 1.0808x; 1.0808x over previous
#include <cuda_runtime.h>
#include <cstdint>

#define N_NODES 50000
#define N_EDGES 800000
#define D 96
#define C4 (D / 4)       // 24 float4 chunks per row
#define NTOT 192         // fused output columns: [0,96)=lin, [96,192)=root

// GEMM tiling
#define MB 128
#define KC 32
#define XS_PITCH (MB + 4)   // pad to reduce store bank conflicts
#define GEMM_THREADS 384    // 16 m-tiles x 24 n-tiles, 8x8 per thread

// Scratch (no allocations allowed)
__device__ float g_h[(size_t)N_NODES * D];   // lin(x) output
__device__ float g_wt[D * NTOT];             // W transposed+fused: [k][n]
__device__ float g_dinv[N_NODES];
__device__ float g_norm[N_EDGES];
__device__ int   g_deg[N_NODES];

// ---------------------------------------------------------------------------
__global__ void k_zero_deg() {
    int i = blockIdx.x * blockDim.x + threadIdx.x;
    if (i < N_NODES) g_deg[i] = 0;
}

__global__ void k_count_deg(const int* __restrict__ dst) {
    int e = blockIdx.x * blockDim.x + threadIdx.x;
    if (e < N_EDGES) atomicAdd(&g_deg[dst[e]], 1);
}

__global__ void k_dinv() {
    int i = blockIdx.x * blockDim.x + threadIdx.x;
    if (i < N_NODES) {
        float d = (float)g_deg[i];
        g_dinv[i] = rsqrtf(fmaxf(d, 1.0f));
    }
}

__global__ void k_norm(const int* __restrict__ src, const int* __restrict__ dst) {
    int e = blockIdx.x * blockDim.x + threadIdx.x;
    if (e < N_EDGES) g_norm[e] = g_dinv[src[e]] * g_dinv[dst[e]];
}

// Pre-transpose + fuse weight matrices: g_wt[k*NTOT + n]
__global__ void k_prep_w(const float* __restrict__ Wlin, const float* __restrict__ Wroot) {
    int idx = blockIdx.x * blockDim.x + threadIdx.x;
    if (idx >= D * NTOT) return;
    int k = idx / NTOT, n = idx - k * NTOT;
    g_wt[idx] = (n < D) ? Wlin[n * D + k] : Wroot[(n - D) * D + k];
}

// ---------------------------------------------------------------------------
// Fused GEMM: for node block of 128 rows, compute x @ [Wlin;Wroot]^T + bias.
// n in [0,96) -> g_h, n in [96,192) -> out (root contribution, init for scatter).
__global__ void __launch_bounds__(GEMM_THREADS)
k_gemm2(const float* __restrict__ x, const float* __restrict__ b_lin,
        const float* __restrict__ b_root, float* __restrict__ out) {
    __shared__ float xs[KC][XS_PITCH];   // x chunk, transposed [k][m]
    __shared__ float ws[KC][NTOT];       // weight chunk [k][n]

    const int tid = threadIdx.x;
    const int mbase = blockIdx.x * MB;
    const int ntile = tid % 24;
    const int mtile = tid / 24;
    const int m0 = mtile * 8;
    const int n0 = ntile * 8;

    // bias init
    float acc[8][8];
    {
        float bias[8];
#pragma unroll
        for (int j = 0; j < 8; j++) {
            int n = n0 + j;
            bias[j] = (n < D) ? b_lin[n] : b_root[n - D];
        }
#pragma unroll
        for (int i = 0; i < 8; i++)
#pragma unroll
            for (int j = 0; j < 8; j++) acc[i][j] = bias[j];
    }

    for (int k0 = 0; k0 < D; k0 += KC) {
        __syncthreads();
        // stage x chunk, transposed: x[mbase+m][k0+kc] -> xs[kc][m]
        for (int t = tid; t < MB * (KC / 4); t += GEMM_THREADS) {
            int m = t >> 3;            // /8
            int kc4 = (t & 7) * 4;
            int gm = mbase + m;
            float4 v = make_float4(0.f, 0.f, 0.f, 0.f);
            if (gm < N_NODES)
                v = *reinterpret_cast<const float4*>(&x[(size_t)gm * D + k0 + kc4]);
            xs[kc4 + 0][m] = v.x;
            xs[kc4 + 1][m] = v.y;
            xs[kc4 + 2][m] = v.z;
            xs[kc4 + 3][m] = v.w;
        }
        // stage weight chunk (coalesced float4)
        {
            const float4* src4 = reinterpret_cast<const float4*>(&g_wt[k0 * NTOT]);
            float4* dst4 = reinterpret_cast<float4*>(&ws[0][0]);
            for (int t = tid; t < KC * NTOT / 4; t += GEMM_THREADS)
                dst4[t] = src4[t];
        }
        __syncthreads();

#pragma unroll 4
        for (int kc = 0; kc < KC; kc++) {
            float4 a0 = *reinterpret_cast<const float4*>(&xs[kc][m0]);
            float4 a1 = *reinterpret_cast<const float4*>(&xs[kc][m0 + 4]);
            float4 w0 = *reinterpret_cast<const float4*>(&ws[kc][n0]);
            float4 w1 = *reinterpret_cast<const float4*>(&ws[kc][n0 + 4]);
            float a[8] = {a0.x, a0.y, a0.z, a0.w, a1.x, a1.y, a1.z, a1.w};
            float w[8] = {w0.x, w0.y, w0.z, w0.w, w1.x, w1.y, w1.z, w1.w};
#pragma unroll
            for (int i = 0; i < 8; i++)
#pragma unroll
                for (int j = 0; j < 8; j++)
                    acc[i][j] = fmaf(a[i], w[j], acc[i][j]);
        }
    }

    // write back: 8 rows x 8 cols per thread
    const bool isroot = (n0 >= D);
    float* base = isroot ? (out + (n0 - D)) : (g_h + n0);
#pragma unroll
    for (int i = 0; i < 8; i++) {
        int m = mbase + m0 + i;
        if (m >= N_NODES) break;
        float* p = base + (size_t)m * D;
        *reinterpret_cast<float4*>(p) =
            make_float4(acc[i][0], acc[i][1], acc[i][2], acc[i][3]);
        *reinterpret_cast<float4*>(p + 4) =
            make_float4(acc[i][4], acc[i][5], acc[i][6], acc[i][7]);
    }
}

// ---------------------------------------------------------------------------
// Edge scatter: out[dst] += norm[e] * h[src], 128-bit vector reductions.
__global__ void k_scatter(const int* __restrict__ src, const int* __restrict__ dst,
                          float* __restrict__ out) {
    int idx = blockIdx.x * blockDim.x + threadIdx.x;
    const int total = N_EDGES * C4;
    if (idx >= total) return;
    int e = idx / C4;
    int c = idx - e * C4;
    int s = src[e];
    int d = dst[e];
    float norm = g_norm[e];
    const float4* hv = reinterpret_cast<const float4*>(g_h);
    float4 v = hv[(size_t)s * C4 + c];
    v.x *= norm; v.y *= norm; v.z *= norm; v.w *= norm;
    float* p = out + (size_t)d * D + c * 4;
    asm volatile("red.global.add.v4.f32 [%0], {%1,%2,%3,%4};"
                 :: "l"(p), "f"(v.x), "f"(v.y), "f"(v.z), "f"(v.w)
                 : "memory");
}

__global__ void k_relu(float* __restrict__ out) {
    int idx = blockIdx.x * blockDim.x + threadIdx.x;
    const int total = N_NODES * C4;
    if (idx >= total) return;
    float4* p = reinterpret_cast<float4*>(out) + idx;
    float4 v = *p;
    v.x = fmaxf(v.x, 0.0f);
    v.y = fmaxf(v.y, 0.0f);
    v.z = fmaxf(v.z, 0.0f);
    v.w = fmaxf(v.w, 0.0f);
    *p = v;
}

// ---------------------------------------------------------------------------
extern "C" void kernel_launch(void* const* d_in, const int* in_sizes, int n_in,
                              void* d_out, int out_size) {
    const float* x     = (const float*)d_in[0];
    const int*   edges = (const int*)d_in[1];
    const float* Wlin  = (const float*)d_in[2];
    const float* blin  = (const float*)d_in[3];
    const float* Wroot = (const float*)d_in[4];
    const float* broot = (const float*)d_in[5];
    float* out = (float*)d_out;

    const int* src = edges;            // edge_index[0, :]
    const int* dst = edges + N_EDGES;  // edge_index[1, :]

    k_prep_w<<<(D * NTOT + 255) / 256, 256>>>(Wlin, Wroot);
    k_zero_deg<<<(N_NODES + 255) / 256, 256>>>();
    k_count_deg<<<(N_EDGES + 255) / 256, 256>>>(dst);
    k_dinv<<<(N_NODES + 255) / 256, 256>>>();
    k_norm<<<(N_EDGES + 255) / 256, 256>>>(src, dst);

    // fused GEMM: writes g_h (lin) and out (root, also scatter init)
    k_gemm2<<<(N_NODES + MB - 1) / MB, GEMM_THREADS>>>(x, blin, broot, out);

    k_scatter<<<(N_EDGES * C4 + 255) / 256, 256>>>(src, dst, out);
    k_relu<<<(N_NODES * C4 + 255) / 256, 256>>>(out);
}

// round 3
// speedup vs baseline: 1.2841x; 1.1881x over previous
#include <cuda_runtime.h>
#include <cstdint>

#define N_NODES 50000
#define N_EDGES 800000
#define D 96
#define NTOT 192         // fused output columns: [0,96)=lin, [96,192)=root

// GEMM tiling
#define MB 128
#define KC 32
#define XS_PITCH (MB + 4)
#define GEMM_THREADS 384

// Scan config
#define SCAN_BS 512
#define SCAN_NBLK ((N_NODES + SCAN_BS - 1) / SCAN_BS)   // 98

// Scratch (no allocations allowed)
__device__ float g_h[(size_t)N_NODES * D];   // lin(x) output
__device__ float g_wt[D * NTOT];             // fused transposed weights [k][n]
__device__ float g_dinv[N_NODES];
__device__ int   g_deg[N_NODES];
__device__ int   g_off[N_NODES];             // CSR row start
__device__ int   g_cur[N_NODES];             // fill cursor
__device__ int   g_csr_src[N_EDGES];         // src node per CSR slot (dst-sorted)
__device__ int   g_bsum[SCAN_NBLK];
__device__ int   g_boff[SCAN_NBLK];

// ---------------------------------------------------------------------------
// 1) init: zero degree counters + prep fused transposed weights
__global__ void k_init(const float* __restrict__ Wlin, const float* __restrict__ Wroot) {
    int i = blockIdx.x * blockDim.x + threadIdx.x;
    if (i < N_NODES) g_deg[i] = 0;
    if (i < D * NTOT) {
        int k = i / NTOT, n = i - k * NTOT;
        g_wt[i] = (n < D) ? Wlin[n * D + k] : Wroot[(n - D) * D + k];
    }
}

// 2) in-degree count
__global__ void k_count_deg(const int* __restrict__ dst) {
    int e = blockIdx.x * blockDim.x + threadIdx.x;
    if (e < N_EDGES) atomicAdd(&g_deg[dst[e]], 1);
}

// ---------------------------------------------------------------------------
// 3-5) exclusive scan of g_deg -> g_off (3-kernel scan) + dinv
__device__ __forceinline__ int warp_incl_scan(int v) {
    int lane = threadIdx.x & 31;
#pragma unroll
    for (int o = 1; o < 32; o <<= 1) {
        int t = __shfl_up_sync(0xffffffffu, v, o);
        if (lane >= o) v += t;
    }
    return v;
}

__global__ void k_scan_sums() {
    __shared__ int wsum[16];
    int tid = threadIdx.x;
    int i = blockIdx.x * SCAN_BS + tid;
    int v = (i < N_NODES) ? g_deg[i] : 0;
#pragma unroll
    for (int o = 16; o; o >>= 1) v += __shfl_down_sync(0xffffffffu, v, o);
    if ((tid & 31) == 0) wsum[tid >> 5] = v;
    __syncthreads();
    if (tid < 16) {
        int s = wsum[tid];
#pragma unroll
        for (int o = 8; o; o >>= 1) s += __shfl_down_sync(0x0000ffffu, s, o);
        if (tid == 0) g_bsum[blockIdx.x] = s;
    }
}

__global__ void k_scan_top() {
    if (threadIdx.x == 0) {
        int r = 0;
        for (int b = 0; b < SCAN_NBLK; b++) { g_boff[b] = r; r += g_bsum[b]; }
    }
}

__global__ void k_scan_final() {
    __shared__ int wsum[16];
    int tid = threadIdx.x;
    int i = blockIdx.x * SCAN_BS + tid;
    int v = (i < N_NODES) ? g_deg[i] : 0;
    int inc = warp_incl_scan(v);
    int wid = tid >> 5, lane = tid & 31;
    if (lane == 31) wsum[wid] = inc;
    __syncthreads();
    if (wid == 0) {
        int s = (lane < 16) ? wsum[lane] : 0;
        s = warp_incl_scan(s);
        if (lane < 16) wsum[lane] = s;
    }
    __syncthreads();
    int ex = inc - v + (wid > 0 ? wsum[wid - 1] : 0);
    if (i < N_NODES) {
        int off = g_boff[blockIdx.x] + ex;
        g_off[i] = off;
        g_cur[i] = off;
        g_dinv[i] = rsqrtf(fmaxf((float)v, 1.0f));
    }
}

// 6) fill CSR: slot = ticket on dst cursor; store src id
__global__ void k_fill(const int* __restrict__ src, const int* __restrict__ dst) {
    int e = blockIdx.x * blockDim.x + threadIdx.x;
    if (e < N_EDGES) {
        int pos = atomicAdd(&g_cur[dst[e]], 1);
        g_csr_src[pos] = src[e];
    }
}

// ---------------------------------------------------------------------------
// 7) Fused GEMM: x @ [Wlin;Wroot]^T + bias. lin -> g_h, root -> out.
__global__ void __launch_bounds__(GEMM_THREADS)
k_gemm2(const float* __restrict__ x, const float* __restrict__ b_lin,
        const float* __restrict__ b_root, float* __restrict__ out) {
    __shared__ float xs[KC][XS_PITCH];
    __shared__ float ws[KC][NTOT];

    const int tid = threadIdx.x;
    const int mbase = blockIdx.x * MB;
    const int ntile = tid % 24;
    const int mtile = tid / 24;
    const int m0 = mtile * 8;
    const int n0 = ntile * 8;

    float acc[8][8];
    {
        float bias[8];
#pragma unroll
        for (int j = 0; j < 8; j++) {
            int n = n0 + j;
            bias[j] = (n < D) ? b_lin[n] : b_root[n - D];
        }
#pragma unroll
        for (int i = 0; i < 8; i++)
#pragma unroll
            for (int j = 0; j < 8; j++) acc[i][j] = bias[j];
    }

    for (int k0 = 0; k0 < D; k0 += KC) {
        __syncthreads();
        for (int t = tid; t < MB * (KC / 4); t += GEMM_THREADS) {
            int m = t >> 3;
            int kc4 = (t & 7) * 4;
            int gm = mbase + m;
            float4 v = make_float4(0.f, 0.f, 0.f, 0.f);
            if (gm < N_NODES)
                v = *reinterpret_cast<const float4*>(&x[(size_t)gm * D + k0 + kc4]);
            xs[kc4 + 0][m] = v.x;
            xs[kc4 + 1][m] = v.y;
            xs[kc4 + 2][m] = v.z;
            xs[kc4 + 3][m] = v.w;
        }
        {
            const float4* s4 = reinterpret_cast<const float4*>(&g_wt[k0 * NTOT]);
            float4* d4 = reinterpret_cast<float4*>(&ws[0][0]);
            for (int t = tid; t < KC * NTOT / 4; t += GEMM_THREADS)
                d4[t] = s4[t];
        }
        __syncthreads();

#pragma unroll 4
        for (int kc = 0; kc < KC; kc++) {
            float4 a0 = *reinterpret_cast<const float4*>(&xs[kc][m0]);
            float4 a1 = *reinterpret_cast<const float4*>(&xs[kc][m0 + 4]);
            float4 w0 = *reinterpret_cast<const float4*>(&ws[kc][n0]);
            float4 w1 = *reinterpret_cast<const float4*>(&ws[kc][n0 + 4]);
            float a[8] = {a0.x, a0.y, a0.z, a0.w, a1.x, a1.y, a1.z, a1.w};
            float w[8] = {w0.x, w0.y, w0.z, w0.w, w1.x, w1.y, w1.z, w1.w};
#pragma unroll
            for (int i = 0; i < 8; i++)
#pragma unroll
                for (int j = 0; j < 8; j++)
                    acc[i][j] = fmaf(a[i], w[j], acc[i][j]);
        }
    }

    const bool isroot = (n0 >= D);
    float* base = isroot ? (out + (n0 - D)) : (g_h + n0);
#pragma unroll
    for (int i = 0; i < 8; i++) {
        int m = mbase + m0 + i;
        if (m >= N_NODES) break;
        float* p = base + (size_t)m * D;
        *reinterpret_cast<float4*>(p) =
            make_float4(acc[i][0], acc[i][1], acc[i][2], acc[i][3]);
        *reinterpret_cast<float4*>(p + 4) =
            make_float4(acc[i][4], acc[i][5], acc[i][6], acc[i][7]);
    }
}

// ---------------------------------------------------------------------------
// 8) aggregation: one warp per dst node. acc = sum over in-edges of norm*h[src];
//    out = relu(acc + root) where root already sits in out. No atomics.
__global__ void __launch_bounds__(256)
k_agg(float* __restrict__ out) {
    int gw = (blockIdx.x * 256 + threadIdx.x) >> 5;
    int lane = threadIdx.x & 31;
    if (gw >= N_NODES) return;

    int beg = g_off[gw];
    int cnt = g_deg[gw];
    int end = beg + cnt;
    float dn = g_dinv[gw];

    float a0 = 0.f, a1 = 0.f, a2 = 0.f;
    int p = beg;
    for (; p + 2 <= end; p += 2) {
        int s0 = g_csr_src[p];
        int s1 = g_csr_src[p + 1];
        float n0 = dn * g_dinv[s0];
        float n1 = dn * g_dinv[s1];
        const float* h0 = g_h + (size_t)s0 * D;
        const float* h1 = g_h + (size_t)s1 * D;
        float v00 = h0[lane], v01 = h0[lane + 32], v02 = h0[lane + 64];
        float v10 = h1[lane], v11 = h1[lane + 32], v12 = h1[lane + 64];
        a0 = fmaf(v00, n0, a0); a1 = fmaf(v01, n0, a1); a2 = fmaf(v02, n0, a2);
        a0 = fmaf(v10, n1, a0); a1 = fmaf(v11, n1, a1); a2 = fmaf(v12, n1, a2);
    }
    if (p < end) {
        int s0 = g_csr_src[p];
        float n0 = dn * g_dinv[s0];
        const float* h0 = g_h + (size_t)s0 * D;
        a0 = fmaf(h0[lane], n0, a0);
        a1 = fmaf(h0[lane + 32], n0, a1);
        a2 = fmaf(h0[lane + 64], n0, a2);
    }

    float* o = out + (size_t)gw * D;
    o[lane]      = fmaxf(a0 + o[lane], 0.f);
    o[lane + 32] = fmaxf(a1 + o[lane + 32], 0.f);
    o[lane + 64] = fmaxf(a2 + o[lane + 64], 0.f);
}

// ---------------------------------------------------------------------------
extern "C" void kernel_launch(void* const* d_in, const int* in_sizes, int n_in,
                              void* d_out, int out_size) {
    const float* x     = (const float*)d_in[0];
    const int*   edges = (const int*)d_in[1];
    const float* Wlin  = (const float*)d_in[2];
    const float* blin  = (const float*)d_in[3];
    const float* Wroot = (const float*)d_in[4];
    const float* broot = (const float*)d_in[5];
    float* out = (float*)d_out;

    const int* src = edges;            // edge_index[0, :]
    const int* dst = edges + N_EDGES;  // edge_index[1, :]

    k_init<<<(N_NODES + 255) / 256, 256>>>(Wlin, Wroot);
    k_count_deg<<<(N_EDGES + 255) / 256, 256>>>(dst);
    k_scan_sums<<<SCAN_NBLK, SCAN_BS>>>();
    k_scan_top<<<1, 32>>>();
    k_scan_final<<<SCAN_NBLK, SCAN_BS>>>();
    k_fill<<<(N_EDGES + 255) / 256, 256>>>(src, dst);

    // fused GEMM: lin -> g_h, root -> out
    k_gemm2<<<(N_NODES + MB - 1) / MB, GEMM_THREADS>>>(x, blin, broot, out);

    // atomic-free aggregation + root add + relu
    k_agg<<<(N_NODES * 32 + 255) / 256, 256>>>(out);
}

// round 4
// speedup vs baseline: 1.5230x; 1.1860x over previous
#include <cuda_runtime.h>
#include <cstdint>

#define N_NODES 50000
#define N_EDGES 800000
#define D 96
#define NTOT 192         // fused output columns: [0,96)=lin, [96,192)=root

// GEMM tiling
#define MB 128
#define KC 32
#define XS_PITCH (MB + 4)
#define GEMM_THREADS 384

// Scan config
#define SCAN_BS 512
#define SCAN_NBLK ((N_NODES + SCAN_BS - 1) / SCAN_BS)   // 98

// Scratch (no allocations allowed)
__device__ float g_h[(size_t)N_NODES * D];   // lin(x) output
__device__ float g_wt[D * NTOT];             // fused transposed weights [k][n]
__device__ float g_dinv[N_NODES];
__device__ int   g_deg[N_NODES];
__device__ int   g_off[N_NODES];             // CSR row start
__device__ int   g_cur[N_NODES];             // fill cursor
__device__ int   g_csr_src[N_EDGES];         // src node per CSR slot (dst-sorted)
__device__ int   g_bsum[SCAN_NBLK];

// ---------------------------------------------------------------------------
// 1) init: zero degree counters + prep fused transposed weights
__global__ void k_init(const float* __restrict__ Wlin, const float* __restrict__ Wroot) {
    int i = blockIdx.x * blockDim.x + threadIdx.x;
    if (i < N_NODES) g_deg[i] = 0;
    if (i < D * NTOT) {
        int k = i / NTOT, n = i - k * NTOT;
        g_wt[i] = (n < D) ? Wlin[n * D + k] : Wroot[(n - D) * D + k];
    }
}

// 2) in-degree count
__global__ void k_count_deg(const int* __restrict__ dst) {
    int e = blockIdx.x * blockDim.x + threadIdx.x;
    if (e < N_EDGES) atomicAdd(&g_deg[dst[e]], 1);
}

// ---------------------------------------------------------------------------
__device__ __forceinline__ int warp_incl_scan(int v) {
    int lane = threadIdx.x & 31;
#pragma unroll
    for (int o = 1; o < 32; o <<= 1) {
        int t = __shfl_up_sync(0xffffffffu, v, o);
        if (lane >= o) v += t;
    }
    return v;
}

// 3) per-block degree sums
__global__ void k_scan_sums() {
    __shared__ int wsum[16];
    int tid = threadIdx.x;
    int i = blockIdx.x * SCAN_BS + tid;
    int v = (i < N_NODES) ? g_deg[i] : 0;
#pragma unroll
    for (int o = 16; o; o >>= 1) v += __shfl_down_sync(0xffffffffu, v, o);
    if ((tid & 31) == 0) wsum[tid >> 5] = v;
    __syncthreads();
    if (tid < 16) {
        int s = wsum[tid];
#pragma unroll
        for (int o = 8; o; o >>= 1) s += __shfl_down_sync(0x0000ffffu, s, o);
        if (tid == 0) g_bsum[blockIdx.x] = s;
    }
}

// 4) final scan: each block computes its own block-prefix from g_bsum (<=98 values),
//    then the in-block exclusive scan. Also writes dinv.
__global__ void k_scan_final() {
    __shared__ int wsum[16];
    __shared__ int s_boff;
    int tid = threadIdx.x;
    int wid = tid >> 5, lane = tid & 31;

    // block prefix: sum of g_bsum[j] for j < blockIdx.x (first warp only)
    if (wid == 0) {
        int bid = blockIdx.x;
        int acc = 0;
#pragma unroll
        for (int base = 0; base < SCAN_NBLK; base += 32) {
            int j = base + lane;
            if (j < bid) acc += g_bsum[j];
        }
#pragma unroll
        for (int o = 16; o; o >>= 1) acc += __shfl_down_sync(0xffffffffu, acc, o);
        if (lane == 0) s_boff = acc;
    }

    int i = blockIdx.x * SCAN_BS + tid;
    int v = (i < N_NODES) ? g_deg[i] : 0;
    int inc = warp_incl_scan(v);
    if (lane == 31) wsum[wid] = inc;
    __syncthreads();
    if (wid == 0) {
        int s = (lane < 16) ? wsum[lane] : 0;
        s = warp_incl_scan(s);
        if (lane < 16) wsum[lane] = s;
    }
    __syncthreads();
    int ex = inc - v + (wid > 0 ? wsum[wid - 1] : 0);
    if (i < N_NODES) {
        int off = s_boff + ex;
        g_off[i] = off;
        g_cur[i] = off;
        g_dinv[i] = rsqrtf(fmaxf((float)v, 1.0f));
    }
}

// 5) fill CSR: slot = ticket on dst cursor; store src id
__global__ void k_fill(const int* __restrict__ src, const int* __restrict__ dst) {
    int e = blockIdx.x * blockDim.x + threadIdx.x;
    if (e < N_EDGES) {
        int pos = atomicAdd(&g_cur[dst[e]], 1);
        g_csr_src[pos] = src[e];
    }
}

// ---------------------------------------------------------------------------
// 6) Fused GEMM: x @ [Wlin;Wroot]^T + bias. lin -> g_h, root -> out.
__global__ void __launch_bounds__(GEMM_THREADS)
k_gemm2(const float* __restrict__ x, const float* __restrict__ b_lin,
        const float* __restrict__ b_root, float* __restrict__ out) {
    __shared__ float xs[KC][XS_PITCH];
    __shared__ float ws[KC][NTOT];

    const int tid = threadIdx.x;
    const int mbase = blockIdx.x * MB;
    const int ntile = tid % 24;
    const int mtile = tid / 24;
    const int m0 = mtile * 8;
    const int n0 = ntile * 8;

    float acc[8][8];
    {
        float bias[8];
#pragma unroll
        for (int j = 0; j < 8; j++) {
            int n = n0 + j;
            bias[j] = (n < D) ? b_lin[n] : b_root[n - D];
        }
#pragma unroll
        for (int i = 0; i < 8; i++)
#pragma unroll
            for (int j = 0; j < 8; j++) acc[i][j] = bias[j];
    }

    for (int k0 = 0; k0 < D; k0 += KC) {
        __syncthreads();
        for (int t = tid; t < MB * (KC / 4); t += GEMM_THREADS) {
            int m = t >> 3;
            int kc4 = (t & 7) * 4;
            int gm = mbase + m;
            float4 v = make_float4(0.f, 0.f, 0.f, 0.f);
            if (gm < N_NODES)
                v = *reinterpret_cast<const float4*>(&x[(size_t)gm * D + k0 + kc4]);
            xs[kc4 + 0][m] = v.x;
            xs[kc4 + 1][m] = v.y;
            xs[kc4 + 2][m] = v.z;
            xs[kc4 + 3][m] = v.w;
        }
        {
            const float4* s4 = reinterpret_cast<const float4*>(&g_wt[k0 * NTOT]);
            float4* d4 = reinterpret_cast<float4*>(&ws[0][0]);
            for (int t = tid; t < KC * NTOT / 4; t += GEMM_THREADS)
                d4[t] = s4[t];
        }
        __syncthreads();

#pragma unroll 4
        for (int kc = 0; kc < KC; kc++) {
            float4 a0 = *reinterpret_cast<const float4*>(&xs[kc][m0]);
            float4 a1 = *reinterpret_cast<const float4*>(&xs[kc][m0 + 4]);
            float4 w0 = *reinterpret_cast<const float4*>(&ws[kc][n0]);
            float4 w1 = *reinterpret_cast<const float4*>(&ws[kc][n0 + 4]);
            float a[8] = {a0.x, a0.y, a0.z, a0.w, a1.x, a1.y, a1.z, a1.w};
            float w[8] = {w0.x, w0.y, w0.z, w0.w, w1.x, w1.y, w1.z, w1.w};
#pragma unroll
            for (int i = 0; i < 8; i++)
#pragma unroll
                for (int j = 0; j < 8; j++)
                    acc[i][j] = fmaf(a[i], w[j], acc[i][j]);
        }
    }

    const bool isroot = (n0 >= D);
    float* base = isroot ? (out + (n0 - D)) : (g_h + n0);
#pragma unroll
    for (int i = 0; i < 8; i++) {
        int m = mbase + m0 + i;
        if (m >= N_NODES) break;
        float* p = base + (size_t)m * D;
        *reinterpret_cast<float4*>(p) =
            make_float4(acc[i][0], acc[i][1], acc[i][2], acc[i][3]);
        *reinterpret_cast<float4*>(p + 4) =
            make_float4(acc[i][4], acc[i][5], acc[i][6], acc[i][7]);
    }
}

// ---------------------------------------------------------------------------
// 7) aggregation: one warp per dst node; relu(acc + root) with root in out.
__global__ void __launch_bounds__(256)
k_agg(float* __restrict__ out) {
    int gw = (blockIdx.x * 256 + threadIdx.x) >> 5;
    int lane = threadIdx.x & 31;
    if (gw >= N_NODES) return;

    int beg = g_off[gw];
    int cnt = g_deg[gw];
    int end = beg + cnt;
    float dn = g_dinv[gw];

    float a0 = 0.f, a1 = 0.f, a2 = 0.f;
    int p = beg;
    for (; p + 2 <= end; p += 2) {
        int s0 = g_csr_src[p];
        int s1 = g_csr_src[p + 1];
        float n0 = dn * g_dinv[s0];
        float n1 = dn * g_dinv[s1];
        const float* h0 = g_h + (size_t)s0 * D;
        const float* h1 = g_h + (size_t)s1 * D;
        float v00 = h0[lane], v01 = h0[lane + 32], v02 = h0[lane + 64];
        float v10 = h1[lane], v11 = h1[lane + 32], v12 = h1[lane + 64];
        a0 = fmaf(v00, n0, a0); a1 = fmaf(v01, n0, a1); a2 = fmaf(v02, n0, a2);
        a0 = fmaf(v10, n1, a0); a1 = fmaf(v11, n1, a1); a2 = fmaf(v12, n1, a2);
    }
    if (p < end) {
        int s0 = g_csr_src[p];
        float n0 = dn * g_dinv[s0];
        const float* h0 = g_h + (size_t)s0 * D;
        a0 = fmaf(h0[lane], n0, a0);
        a1 = fmaf(h0[lane + 32], n0, a1);
        a2 = fmaf(h0[lane + 64], n0, a2);
    }

    float* o = out + (size_t)gw * D;
    o[lane]      = fmaxf(a0 + o[lane], 0.f);
    o[lane + 32] = fmaxf(a1 + o[lane + 32], 0.f);
    o[lane + 64] = fmaxf(a2 + o[lane + 64], 0.f);
}

// ---------------------------------------------------------------------------
extern "C" void kernel_launch(void* const* d_in, const int* in_sizes, int n_in,
                              void* d_out, int out_size) {
    const float* x     = (const float*)d_in[0];
    const int*   edges = (const int*)d_in[1];
    const float* Wlin  = (const float*)d_in[2];
    const float* blin  = (const float*)d_in[3];
    const float* Wroot = (const float*)d_in[4];
    const float* broot = (const float*)d_in[5];
    float* out = (float*)d_out;

    const int* src = edges;            // edge_index[0, :]
    const int* dst = edges + N_EDGES;  // edge_index[1, :]

    // Created once on first (non-captured correctness) call; reused across
    // captures. Host-side objects only — no device memory involved.
    static cudaStream_t s2 = []() {
        cudaStream_t s; cudaStreamCreateWithFlags(&s, cudaStreamNonBlocking); return s;
    }();
    static cudaEvent_t ev_init = []() {
        cudaEvent_t e; cudaEventCreateWithFlags(&e, cudaEventDisableTiming); return e;
    }();
    static cudaEvent_t ev_gemm = []() {
        cudaEvent_t e; cudaEventCreateWithFlags(&e, cudaEventDisableTiming); return e;
    }();

    // common init (zero deg + fused transposed weights)
    k_init<<<(N_NODES + 255) / 256, 256>>>(Wlin, Wroot);
    cudaEventRecord(ev_init, 0);

    // branch A (s2): fused GEMM (needs g_wt from k_init)
    cudaStreamWaitEvent(s2, ev_init, 0);
    k_gemm2<<<(N_NODES + MB - 1) / MB, GEMM_THREADS, 0, s2>>>(x, blin, broot, out);
    cudaEventRecord(ev_gemm, s2);

    // branch B (capture stream): CSR build
    k_count_deg<<<(N_EDGES + 255) / 256, 256>>>(dst);
    k_scan_sums<<<SCAN_NBLK, SCAN_BS>>>();
    k_scan_final<<<SCAN_NBLK, SCAN_BS>>>();
    k_fill<<<(N_EDGES + 255) / 256, 256>>>(src, dst);

    // join: aggregation needs both branches
    cudaStreamWaitEvent(0, ev_gemm, 0);
    k_agg<<<(N_NODES * 32 + 255) / 256, 256>>>(out);
}